// round 7
// baseline (speedup 1.0000x reference)
#include <cuda_runtime.h>
#include <math.h>

#define EPS 1e-12f

// ---------------- persistent scratch ----------------------------------------
__device__ float g_wn1[80 * 75];
__device__ float g_e1[80];
__device__ float g_wn2d[80 * 9];
__device__ float g_e2d[80];
__device__ float g_wn2p[40 * 80];
__device__ float g_e2p[40];
__device__ float g_wn3[40 * 360];
__device__ float g_e3[40];
__device__ float g_qv[4];

// full-resolution intermediates (reference-mirroring)
__device__ float B1G[1024 * 80 * 28 * 28];   // layer1 g-output (pre-pool)
__device__ float B1P[1024 * 80 * 14 * 14];   // pooled
__device__ float B2D[1024 * 80 * 12 * 12];   // depthwise g-output
__device__ float B2P[1024 * 40 * 12 * 12];   // pointwise g-output (pre-pool)
__device__ float B2Q[1024 * 40 * 6 * 6];     // pooled
__device__ float B3[1024 * 40 * 4 * 4];      // layer3 g-output (pre-pool)
__device__ float B3P[1024 * 40];             // pooled

// g(y) = sign(y) * (|y|+EPS)^e   (libdevice powf — matches XLA's pow lowering)
__device__ __forceinline__ float scs_g(float y, float e) {
    float a = __fadd_rn(fabsf(y), EPS);
    float r = powf(a, e);
    return (y > 0.f) ? r : ((y < 0.f) ? -r : 0.f);
}

// ---------------- weight prep: XLA-style warp row-reduce --------------------
// sum of squares: squares rounded separately (__fmul_rn), strided lane
// partials, then shfl-down tree 16..1 (XLA GPU row-reduction shape).
__global__ void prep_kernel(const float* w1, const float* p1, const float* q1,
                            const float* w2d, const float* p2d, const float* q2d,
                            const float* w2p, const float* p2p, const float* q2p,
                            const float* w3, const float* p3, const float* q3) {
    int b = blockIdx.x, t = threadIdx.x;
    const float *w, *p, *q;
    float *wn, *e;
    int n, c, li;
    if (b < 80)       { c = b;       w = w1  + c * 75;  n = 75;  wn = g_wn1  + c * 75;  p = p1;  q = q1;  e = g_e1;  li = 0; }
    else if (b < 160) { c = b - 80;  w = w2d + c * 9;   n = 9;   wn = g_wn2d + c * 9;   p = p2d; q = q2d; e = g_e2d; li = 1; }
    else if (b < 200) { c = b - 160; w = w2p + c * 80;  n = 80;  wn = g_wn2p + c * 80;  p = p2p; q = q2p; e = g_e2p; li = 2; }
    else              { c = b - 200; w = w3  + c * 360; n = 360; wn = g_wn3  + c * 360; p = p3;  q = q3;  e = g_e3;  li = 3; }
    float qt = __fdiv_rn(q[0], 100.0f);
    float qv = __fmul_rn(qt, qt);
    float s = 0.f;
    for (int i = t; i < n; i += 32) {
        float v = w[i];
        s = __fadd_rn(s, __fmul_rn(v, v));   // square rounded, then add
    }
    #pragma unroll
    for (int o = 16; o > 0; o >>= 1)
        s = __fadd_rn(s, __shfl_down_sync(0xffffffffu, s, o));
    s = __shfl_sync(0xffffffffu, s, 0);
    float wnorm = __fadd_rn(sqrtf(__fadd_rn(s, EPS)), qv);
    for (int i = t; i < n; i += 32) wn[i] = __fdiv_rn(w[i], wnorm);
    if (t == 0) {
        float pe = __fdiv_rn(p[c], 10.0f);
        e[c] = __fmul_rn(pe, pe);
        if (c == 0) g_qv[li] = qv;
    }
}

// ---------------- layer1: 5x5 conv (3->80), scs -----------------------------
// reduction order (ky, kx, c) with c innermost (NHWC-style im2col order);
// num via sequential FMA, sq via rounded-square + add.
__global__ void k1(const float* x, int total) {
    int idx = blockIdx.x * 256 + threadIdx.x;
    if (idx >= total) return;
    int ox = idx % 28;
    int t = idx / 28;
    int oy = t % 28; t /= 28;
    int o = t % 80;
    int n = t / 80;
    const float* xp = x + n * 3072;
    const float* wp = g_wn1 + o * 75;
    float num = 0.f, ss = 0.f;
    #pragma unroll
    for (int ky = 0; ky < 5; ky++)
        #pragma unroll
        for (int kx = 0; kx < 5; kx++)
            #pragma unroll
            for (int c = 0; c < 3; c++) {
                float v = __ldg(&xp[c * 1024 + (oy + ky) * 32 + ox + kx]);
                num = fmaf(wp[c * 25 + ky * 5 + kx], v, num);
                ss  = __fadd_rn(ss, __fmul_rn(v, v));
            }
    float xn = __fadd_rn(sqrtf(__fadd_rn(ss, EPS)), g_qv[0]);
    float y = __fdiv_rn(num, xn);
    B1G[idx] = scs_g(y, g_e1[o]);
}

// ---------------- generic maxabs pool (exact; order-independent) ------------
__global__ void maxabs_k(const float* in, float* out, int total,
                         int Hi, int Wi, int Ho, int Wo, int k, int s) {
    int idx = blockIdx.x * 256 + threadIdx.x;
    if (idx >= total) return;
    int ox = idx % Wo;
    int oy = (idx / Wo) % Ho;
    int cn = idx / (Wo * Ho);
    const float* base = in + cn * Hi * Wi;
    float pos = -3.402823466e38f, neg = 3.402823466e38f;
    for (int ky = 0; ky < k; ky++)
        for (int kx = 0; kx < k; kx++) {
            float v = base[(oy * s + ky) * Wi + ox * s + kx];
            pos = fmaxf(pos, v);
            neg = fminf(neg, v);
        }
    out[idx] = (pos >= -neg) ? pos : neg;
}

// ---------------- layer2 depthwise 3x3 (80 groups), scs ---------------------
__global__ void k2d(int total) {
    int idx = blockIdx.x * 256 + threadIdx.x;
    if (idx >= total) return;
    int ox = idx % 12;
    int t = idx / 12;
    int oy = t % 12; t /= 12;
    int ch = t % 80;
    int n = t / 80;
    const float* in = B1P + (n * 80 + ch) * 196;
    const float* wp = g_wn2d + ch * 9;
    float num = 0.f, ss = 0.f;
    #pragma unroll
    for (int ky = 0; ky < 3; ky++)
        #pragma unroll
        for (int kx = 0; kx < 3; kx++) {
            float v = in[(oy + ky) * 14 + ox + kx];
            num = fmaf(wp[ky * 3 + kx], v, num);
            ss  = __fadd_rn(ss, __fmul_rn(v, v));
        }
    float y = __fdiv_rn(num, __fadd_rn(sqrtf(__fadd_rn(ss, EPS)), g_qv[1]));
    B2D[idx] = scs_g(y, g_e2d[ch]);
}

// ---------------- layer2 pointwise 1x1 (80->40), scs ------------------------
__global__ void k2p(int total) {
    int idx = blockIdx.x * 256 + threadIdx.x;
    if (idx >= total) return;
    int pix = idx % 144;
    int t = idx / 144;
    int o = t % 40;
    int n = t / 40;
    const float* in = B2D + n * 80 * 144;
    const float* wp = g_wn2p + o * 80;
    float num = 0.f, ss = 0.f;
    for (int k = 0; k < 80; k++) {
        float v = in[k * 144 + pix];
        num = fmaf(wp[k], v, num);
        ss  = __fadd_rn(ss, __fmul_rn(v, v));
    }
    float y = __fdiv_rn(num, __fadd_rn(sqrtf(__fadd_rn(ss, EPS)), g_qv[2]));
    B2P[idx] = scs_g(y, g_e2p[o]);
}

// ---------------- layer3: 3x3 conv (40->40), scs -----------------------------
// reduction order (ky, kx, c) with c innermost.
__global__ void k3(int total) {
    int idx = blockIdx.x * 256 + threadIdx.x;
    if (idx >= total) return;
    int ox = idx % 4;
    int t = idx / 4;
    int oy = t % 4; t /= 4;
    int o = t % 40;
    int n = t / 40;
    const float* in = B2Q + n * 40 * 36;
    const float* wp = g_wn3 + o * 360;
    float num = 0.f, ss = 0.f;
    #pragma unroll
    for (int ky = 0; ky < 3; ky++)
        #pragma unroll
        for (int kx = 0; kx < 3; kx++)
            for (int c = 0; c < 40; c++) {
                float v = in[c * 36 + (oy + ky) * 6 + ox + kx];
                num = fmaf(wp[c * 9 + ky * 3 + kx], v, num);
                ss  = __fadd_rn(ss, __fmul_rn(v, v));
            }
    float y = __fdiv_rn(num, __fadd_rn(sqrtf(__fadd_rn(ss, EPS)), g_qv[3]));
    B3[idx] = scs_g(y, g_e3[o]);
}

// ---------------- FC: dot from zero, bias added after (GEMM semantics) ------
__global__ void kfc(const float* wo, const float* bo, float* out, int total) {
    int idx = blockIdx.x * 256 + threadIdx.x;
    if (idx >= total) return;
    int j = idx % 10;
    int n = idx / 10;
    float s = 0.f;
    const float* tv = B3P + n * 40;
    const float* wj = wo + j * 40;
    for (int c = 0; c < 40; c++) s = fmaf(tv[c], wj[c], s);
    out[idx] = __fadd_rn(s, bo[j]);
}

// ---------------- launch ------------------------------------------------------
extern "C" void kernel_launch(void* const* d_in, const int* in_sizes, int n_in,
                              void* d_out, int out_size) {
    const float* x   = (const float*)d_in[0];
    const float* w1  = (const float*)d_in[1];
    const float* p1  = (const float*)d_in[2];
    const float* q1  = (const float*)d_in[3];
    const float* w2d = (const float*)d_in[4];
    const float* p2d = (const float*)d_in[5];
    const float* q2d = (const float*)d_in[6];
    const float* w2p = (const float*)d_in[7];
    const float* p2p = (const float*)d_in[8];
    const float* q2p = (const float*)d_in[9];
    const float* w3  = (const float*)d_in[10];
    const float* p3  = (const float*)d_in[11];
    const float* q3  = (const float*)d_in[12];
    const float* wo  = (const float*)d_in[13];
    const float* bo  = (const float*)d_in[14];
    float* out = (float*)d_out;

    int N = in_sizes[0] / 3072;

    float *b1g, *b1p, *b2p, *b3;
    cudaGetSymbolAddress((void**)&b1g, B1G);
    cudaGetSymbolAddress((void**)&b1p, B1P);
    cudaGetSymbolAddress((void**)&b2p, B2P);
    cudaGetSymbolAddress((void**)&b3,  B3);
    float *b2q, *b3p;
    cudaGetSymbolAddress((void**)&b2q, B2Q);
    cudaGetSymbolAddress((void**)&b3p, B3P);

    prep_kernel<<<240, 32>>>(w1, p1, q1, w2d, p2d, q2d, w2p, p2p, q2p, w3, p3, q3);

    int t1 = N * 80 * 28 * 28;
    k1<<<(t1 + 255) / 256, 256>>>(x, t1);

    int tp1 = N * 80 * 14 * 14;
    maxabs_k<<<(tp1 + 255) / 256, 256>>>(b1g, b1p, tp1, 28, 28, 14, 14, 2, 2);

    int t2d = N * 80 * 12 * 12;
    k2d<<<(t2d + 255) / 256, 256>>>(t2d);

    int t2p = N * 40 * 12 * 12;
    k2p<<<(t2p + 255) / 256, 256>>>(t2p);

    int tp2 = N * 40 * 6 * 6;
    maxabs_k<<<(tp2 + 255) / 256, 256>>>(b2p, b2q, tp2, 12, 12, 6, 6, 2, 2);

    int t3 = N * 40 * 4 * 4;
    k3<<<(t3 + 255) / 256, 256>>>(t3);

    int tp3 = N * 40;
    maxabs_k<<<(tp3 + 255) / 256, 256>>>(b3, b3p, tp3, 4, 4, 1, 1, 4, 4);

    int tf = N * 10;
    kfc<<<(tf + 255) / 256, 256>>>(wo, bo, out, tf);
}

// round 8
// speedup vs baseline: 2.8483x; 2.8483x over previous
#include <cuda_runtime.h>
#include <math.h>

#define EPS 1e-12f

// ---------------- persistent scratch ----------------------------------------
__device__ float g_wn1[80 * 75];
__device__ float g_e1[80];
__device__ float g_wn2d[80 * 9];
__device__ float g_e2d[80];
__device__ float g_wn2p[40 * 80];
__device__ float g_e2p[40];
__device__ float g_wn3[40 * 360];
__device__ float g_e3[40];
__device__ float g_qv[4];

__device__ float g_xn1[1024 * 784];           // layer1 patch-norm DENOMINATORS
__device__ float g_buf1[1024 * 80 * 14 * 14]; // pooled layer1 g-output
__device__ float g_buf2[1024 * 40 * 6 * 6];   // pooled layer2 g-output

// g(y) = sign(y) * (|y|+EPS)^e   (libdevice powf — matches reference)
__device__ __forceinline__ float scs_g(float y, float e) {
    float a = __fadd_rn(fabsf(y), EPS);
    float r = powf(a, e);
    return (y > 0.f) ? r : ((y < 0.f) ? -r : 0.f);
}

// maxabs select over pos/neg extrema (exact, order-independent)
__device__ __forceinline__ float maxabs4(float a, float b, float c, float d) {
    float pmx = fmaxf(fmaxf(a, b), fmaxf(c, d));
    float pmn = fminf(fminf(a, b), fminf(c, d));
    return (pmx >= -pmn) ? pmx : pmn;
}

// ---------------- weight prep (bit-identical to round 7) --------------------
__global__ void prep_kernel(const float* w1, const float* p1, const float* q1,
                            const float* w2d, const float* p2d, const float* q2d,
                            const float* w2p, const float* p2p, const float* q2p,
                            const float* w3, const float* p3, const float* q3) {
    int b = blockIdx.x, t = threadIdx.x;
    const float *w, *p, *q;
    float *wn, *e;
    int n, c, li;
    if (b < 80)       { c = b;       w = w1  + c * 75;  n = 75;  wn = g_wn1  + c * 75;  p = p1;  q = q1;  e = g_e1;  li = 0; }
    else if (b < 160) { c = b - 80;  w = w2d + c * 9;   n = 9;   wn = g_wn2d + c * 9;   p = p2d; q = q2d; e = g_e2d; li = 1; }
    else if (b < 200) { c = b - 160; w = w2p + c * 80;  n = 80;  wn = g_wn2p + c * 80;  p = p2p; q = q2p; e = g_e2p; li = 2; }
    else              { c = b - 200; w = w3  + c * 360; n = 360; wn = g_wn3  + c * 360; p = p3;  q = q3;  e = g_e3;  li = 3; }
    float qt = __fdiv_rn(q[0], 100.0f);
    float qv = __fmul_rn(qt, qt);
    float s = 0.f;
    for (int i = t; i < n; i += 32) {
        float v = w[i];
        s = __fadd_rn(s, __fmul_rn(v, v));
    }
    #pragma unroll
    for (int o = 16; o > 0; o >>= 1)
        s = __fadd_rn(s, __shfl_down_sync(0xffffffffu, s, o));
    s = __shfl_sync(0xffffffffu, s, 0);
    float wnorm = __fadd_rn(sqrtf(__fadd_rn(s, EPS)), qv);
    for (int i = t; i < n; i += 32) wn[i] = __fdiv_rn(w[i], wnorm);
    if (t == 0) {
        float pe = __fdiv_rn(p[c], 10.0f);
        e[c] = __fmul_rn(pe, pe);
        if (c == 0) g_qv[li] = qv;
    }
}

// ---------------- layer1 patch norms: ss in (ky,kx,c) order -----------------
__global__ void xnorm1_kernel(const float* x) {
    __shared__ float sx[3072];
    int img = blockIdx.x;
    const float* xp = x + img * 3072;
    for (int i = threadIdx.x; i < 3072; i += 256) sx[i] = xp[i];
    __syncthreads();
    float qv = g_qv[0];
    for (int pos = threadIdx.x; pos < 784; pos += 256) {
        int oy = pos / 28, ox = pos % 28;
        float ss = 0.f;
        #pragma unroll
        for (int ky = 0; ky < 5; ky++)
            #pragma unroll
            for (int kx = 0; kx < 5; kx++)
                #pragma unroll
                for (int c = 0; c < 3; c++) {
                    float v = sx[c * 1024 + (oy + ky) * 32 + ox + kx];
                    ss = __fadd_rn(ss, __fmul_rn(v, v));
                }
        g_xn1[img * 784 + pos] = __fadd_rn(sqrtf(__fadd_rn(ss, EPS)), qv);
    }
}

// ---------------- layer1: conv 5x5 (3->80) + pool 2x2 + g -------------------
// per-output num reduction in exact (ky,kx,c) fmaf order; tile 8 outch x
// (2 rows x 4 cols) per thread; pool-then-g (bit-exact commute).
__global__ void __launch_bounds__(224) conv1_kernel(const float* x) {
    __shared__ float sx[3072];
    __shared__ float sw[16 * 75];
    __shared__ float sxn[784];
    __shared__ float se[16];
    int img = blockIdx.x;
    int cb = blockIdx.y * 16;
    const float* xp = x + img * 3072;
    for (int i = threadIdx.x; i < 3072; i += 224) sx[i] = xp[i];
    for (int i = threadIdx.x; i < 1200; i += 224) sw[i] = g_wn1[cb * 75 + i];
    for (int i = threadIdx.x; i < 784; i += 224) sxn[i] = g_xn1[img * 784 + i];
    if (threadIdx.x < 16) se[threadIdx.x] = g_e1[cb + threadIdx.x];
    __syncthreads();
    int tid = threadIdx.x;
    if (tid >= 196) return;
    int ct = tid / 98, pp = tid % 98;
    int py = pp / 7;          // pooled row 0..13
    int pq = pp % 7;          // pooled col pair 0..6
    int cx0 = 4 * pq;         // conv col base (4 conv cols)

    float acc[8][8];
    #pragma unroll
    for (int a = 0; a < 8; a++)
        #pragma unroll
        for (int b2 = 0; b2 < 8; b2++) acc[a][b2] = 0.f;

    #pragma unroll 1
    for (int ky = 0; ky < 5; ky++) {
        const float* xr = &sx[(2 * py + ky) * 32 + cx0];
        #pragma unroll
        for (int kx = 0; kx < 5; kx++) {
            #pragma unroll
            for (int c = 0; c < 3; c++) {
                float xv[2][4];
                #pragma unroll
                for (int r = 0; r < 2; r++)
                    #pragma unroll
                    for (int cl = 0; cl < 4; cl++)
                        xv[r][cl] = xr[c * 1024 + r * 32 + kx + cl];
                int widx = c * 25 + ky * 5 + kx;
                #pragma unroll
                for (int t = 0; t < 8; t++) {
                    float w = sw[(ct * 8 + t) * 75 + widx];
                    #pragma unroll
                    for (int r = 0; r < 2; r++)
                        #pragma unroll
                        for (int cl = 0; cl < 4; cl++)
                            acc[t][r * 4 + cl] = fmaf(w, xv[r][cl], acc[t][r * 4 + cl]);
                }
            }
        }
    }
    float xnv[8];
    #pragma unroll
    for (int r = 0; r < 2; r++)
        #pragma unroll
        for (int cl = 0; cl < 4; cl++)
            xnv[r * 4 + cl] = sxn[(2 * py + r) * 28 + cx0 + cl];

    int ob = ((img * 80 + cb + ct * 8) * 14 + py) * 14 + 2 * pq;
    #pragma unroll
    for (int t = 0; t < 8; t++) {
        float y[8];
        #pragma unroll
        for (int j = 0; j < 8; j++) y[j] = __fdiv_rn(acc[t][j], xnv[j]);
        float e = se[ct * 8 + t];
        float v0 = maxabs4(y[0], y[1], y[4], y[5]);   // pooled pair 0 (cols 0,1)
        float v1 = maxabs4(y[2], y[3], y[6], y[7]);   // pooled pair 1 (cols 2,3)
        g_buf1[ob + t * 196]     = scs_g(v0, e);
        g_buf1[ob + t * 196 + 1] = scs_g(v1, e);
    }
}

// ---------------- layer2: depthwise 3x3 + pointwise 1x1 + pool + g ----------
__global__ void __launch_bounds__(512) layer2_kernel() {
    extern __shared__ float sm[];
    float* s_t1  = sm;               // 15680
    float* s_t2d = sm + 15680;       // 11520
    float* s_w2d = s_t2d + 11520;    // 720
    float* s_w2p = s_w2d + 720;      // 3200
    float* s_e2d = s_w2p + 3200;     // 80
    float* s_e2p = s_e2d + 80;       // 40
    float* s_xn  = s_e2p + 40;       // 144 (denominators)
    int img = blockIdx.x, tid = threadIdx.x;

    const float4* src = (const float4*)(g_buf1 + img * 15680);
    for (int i = tid; i < 15680 / 4; i += 512) ((float4*)s_t1)[i] = src[i];
    for (int i = tid; i < 720; i += 512) s_w2d[i] = g_wn2d[i];
    for (int i = tid; i < 3200; i += 512) s_w2p[i] = g_wn2p[i];
    if (tid < 80) s_e2d[tid] = g_e2d[tid];
    if (tid < 40) s_e2p[tid] = g_e2p[tid];
    __syncthreads();
    float qv2d = g_qv[1], qv2p = g_qv[2];

    // depthwise scs (80ch, 14x14 -> 12x12); reduction order (ky,kx)
    for (int tile = tid; tile < 960; tile += 512) {
        int ch = tile / 12, oy = tile % 12;
        float wreg[9];
        #pragma unroll
        for (int k = 0; k < 9; k++) wreg[k] = s_w2d[ch * 9 + k];
        float e = s_e2d[ch];
        const float* xr = &s_t1[ch * 196 + oy * 14];
        float rw[3][14];
        #pragma unroll
        for (int rr = 0; rr < 3; rr++)
            #pragma unroll
            for (int j = 0; j < 14; j++) rw[rr][j] = xr[rr * 14 + j];
        #pragma unroll
        for (int ox = 0; ox < 12; ox++) {
            float num = 0.f, ss = 0.f;
            #pragma unroll
            for (int ky = 0; ky < 3; ky++)
                #pragma unroll
                for (int kx = 0; kx < 3; kx++) {
                    float v = rw[ky][ox + kx];
                    num = fmaf(wreg[ky * 3 + kx], v, num);
                    ss  = __fadd_rn(ss, __fmul_rn(v, v));
                }
            float y = __fdiv_rn(num, __fadd_rn(sqrtf(__fadd_rn(ss, EPS)), qv2d));
            s_t2d[ch * 144 + oy * 12 + ox] = scs_g(y, e);
        }
    }
    __syncthreads();

    // per-pixel channel-norm denominators (k-sequential)
    for (int pix = tid; pix < 144; pix += 512) {
        float ss = 0.f;
        for (int k = 0; k < 80; k++) {
            float v = s_t2d[k * 144 + pix];
            ss = __fadd_rn(ss, __fmul_rn(v, v));
        }
        s_xn[pix] = __fadd_rn(sqrtf(__fadd_rn(ss, EPS)), qv2p);
    }
    __syncthreads();

    // pointwise (80->40, k-sequential fmaf) + pool 2x2 + g
    for (int tile = tid; tile < 360; tile += 512) {
        int cg = tile / 36, quad = tile % 36;
        int qy = quad / 6, qx = quad % 6;
        int p00 = (2 * qy) * 12 + 2 * qx;
        int p01 = p00 + 1, p10 = p00 + 12, p11 = p00 + 13;
        float acc[4][4];
        #pragma unroll
        for (int i = 0; i < 4; i++)
            #pragma unroll
            for (int j = 0; j < 4; j++) acc[i][j] = 0.f;
        for (int k = 0; k < 80; k++) {
            float x0 = s_t2d[k * 144 + p00], x1 = s_t2d[k * 144 + p01];
            float x2 = s_t2d[k * 144 + p10], x3 = s_t2d[k * 144 + p11];
            #pragma unroll
            for (int i = 0; i < 4; i++) {
                float w = s_w2p[(cg * 4 + i) * 80 + k];
                acc[i][0] = fmaf(w, x0, acc[i][0]);
                acc[i][1] = fmaf(w, x1, acc[i][1]);
                acc[i][2] = fmaf(w, x2, acc[i][2]);
                acc[i][3] = fmaf(w, x3, acc[i][3]);
            }
        }
        float n0 = s_xn[p00], n1 = s_xn[p01], n2 = s_xn[p10], n3 = s_xn[p11];
        #pragma unroll
        for (int i = 0; i < 4; i++) {
            float y0 = __fdiv_rn(acc[i][0], n0);
            float y1 = __fdiv_rn(acc[i][1], n1);
            float y2 = __fdiv_rn(acc[i][2], n2);
            float y3 = __fdiv_rn(acc[i][3], n3);
            float v = maxabs4(y0, y1, y2, y3);
            int co = cg * 4 + i;
            g_buf2[((img * 40 + co) * 6 + qy) * 6 + qx] = scs_g(v, s_e2p[co]);
        }
    }
}

// ---------------- layer3: conv 3x3 (40->40) + pool 4x4 + g + FC -------------
__global__ void __launch_bounds__(160) layer3_kernel(const float* wo, const float* bo, float* out) {
    extern __shared__ float sm[];
    float* s_in   = sm;              // 1440
    float* s_w3   = sm + 1440;       // 14400
    float* s_wo   = s_w3 + 14400;    // 400
    float* s_e3   = s_wo + 400;      // 40
    float* s_xn   = s_e3 + 40;       // 16 (denominators)
    float* s_qmax = s_xn + 16;       // 160
    float* s_qmin = s_qmax + 160;    // 160
    float* s_vec  = s_qmin + 160;    // 40
    float* s_bo   = s_vec + 40;      // 16 (pad)
    int img = blockIdx.x, tid = threadIdx.x;

    const float4* src = (const float4*)(g_buf2 + img * 1440);
    for (int i = tid; i < 360; i += 160) ((float4*)s_in)[i] = src[i];
    for (int i = tid; i < 3600; i += 160) ((float4*)s_w3)[i] = ((const float4*)g_wn3)[i];
    for (int i = tid; i < 400; i += 160) s_wo[i] = wo[i];
    if (tid < 40) s_e3[tid] = g_e3[tid];
    if (tid < 10) s_bo[tid] = bo[tid];
    __syncthreads();
    float qv3 = g_qv[3];

    if (tid < 16) {   // patch norms: (ky,kx,c) order, c innermost
        int oy = tid / 4, ox = tid % 4;
        float ss = 0.f;
        #pragma unroll
        for (int ky = 0; ky < 3; ky++)
            #pragma unroll
            for (int kx = 0; kx < 3; kx++)
                for (int c = 0; c < 40; c++) {
                    float v = s_in[c * 36 + (oy + ky) * 6 + ox + kx];
                    ss = __fadd_rn(ss, __fmul_rn(v, v));
                }
        s_xn[tid] = __fadd_rn(sqrtf(__fadd_rn(ss, EPS)), qv3);
    }
    __syncthreads();

    {   // conv: (ky,kx,c) order c innermost; thread = (out-ch, 2x2 quad)
        int co = tid >> 2, quad = tid & 3;
        int qy = quad >> 1, qx = quad & 1;
        float acc[4] = {0.f, 0.f, 0.f, 0.f};
        #pragma unroll
        for (int ky = 0; ky < 3; ky++)
            #pragma unroll
            for (int kx = 0; kx < 3; kx++)
                for (int c = 0; c < 40; c++) {
                    float w = s_w3[(co * 40 + c) * 9 + ky * 3 + kx];
                    const float* ip = &s_in[c * 36];
                    acc[0] = fmaf(w, ip[(2 * qy + ky) * 6 + 2 * qx + kx], acc[0]);
                    acc[1] = fmaf(w, ip[(2 * qy + ky) * 6 + 2 * qx + 1 + kx], acc[1]);
                    acc[2] = fmaf(w, ip[(2 * qy + 1 + ky) * 6 + 2 * qx + kx], acc[2]);
                    acc[3] = fmaf(w, ip[(2 * qy + 1 + ky) * 6 + 2 * qx + 1 + kx], acc[3]);
                }
        float y0 = __fdiv_rn(acc[0], s_xn[(2 * qy) * 4 + 2 * qx]);
        float y1 = __fdiv_rn(acc[1], s_xn[(2 * qy) * 4 + 2 * qx + 1]);
        float y2 = __fdiv_rn(acc[2], s_xn[(2 * qy + 1) * 4 + 2 * qx]);
        float y3 = __fdiv_rn(acc[3], s_xn[(2 * qy + 1) * 4 + 2 * qx + 1]);
        s_qmax[tid] = fmaxf(fmaxf(y0, y1), fmaxf(y2, y3));
        s_qmin[tid] = fminf(fminf(y0, y1), fminf(y2, y3));
    }
    __syncthreads();
    if (tid < 40) {   // pool 4x4 (via quad extrema) then g
        float pmx = fmaxf(fmaxf(s_qmax[tid * 4], s_qmax[tid * 4 + 1]),
                          fmaxf(s_qmax[tid * 4 + 2], s_qmax[tid * 4 + 3]));
        float pmn = fminf(fminf(s_qmin[tid * 4], s_qmin[tid * 4 + 1]),
                          fminf(s_qmin[tid * 4 + 2], s_qmin[tid * 4 + 3]));
        float v = (pmx >= -pmn) ? pmx : pmn;
        s_vec[tid] = scs_g(v, s_e3[tid]);
    }
    __syncthreads();
    if (tid < 10) {   // FC: dot from zero (sequential fmaf), bias after
        float s = 0.f;
        #pragma unroll 1
        for (int c = 0; c < 40; c++) s = fmaf(s_vec[c], s_wo[tid * 40 + c], s);
        out[img * 10 + tid] = __fadd_rn(s, s_bo[tid]);
    }
}

// ---------------- launch ------------------------------------------------------
extern "C" void kernel_launch(void* const* d_in, const int* in_sizes, int n_in,
                              void* d_out, int out_size) {
    const float* x   = (const float*)d_in[0];
    const float* w1  = (const float*)d_in[1];
    const float* p1  = (const float*)d_in[2];
    const float* q1  = (const float*)d_in[3];
    const float* w2d = (const float*)d_in[4];
    const float* p2d = (const float*)d_in[5];
    const float* q2d = (const float*)d_in[6];
    const float* w2p = (const float*)d_in[7];
    const float* p2p = (const float*)d_in[8];
    const float* q2p = (const float*)d_in[9];
    const float* w3  = (const float*)d_in[10];
    const float* p3  = (const float*)d_in[11];
    const float* q3  = (const float*)d_in[12];
    const float* wo  = (const float*)d_in[13];
    const float* bo  = (const float*)d_in[14];
    float* out = (float*)d_out;

    int N = in_sizes[0] / 3072;

    static const size_t SM2 = (15680 + 11520 + 720 + 3200 + 80 + 40 + 144) * sizeof(float);
    static const size_t SM3 = (1440 + 14400 + 400 + 40 + 16 + 160 + 160 + 40 + 16) * sizeof(float);
    cudaFuncSetAttribute(layer2_kernel, cudaFuncAttributeMaxDynamicSharedMemorySize, (int)SM2);
    cudaFuncSetAttribute(layer3_kernel, cudaFuncAttributeMaxDynamicSharedMemorySize, (int)SM3);

    prep_kernel<<<240, 32>>>(w1, p1, q1, w2d, p2d, q2d, w2p, p2p, q2p, w3, p3, q3);
    xnorm1_kernel<<<N, 256>>>(x);
    conv1_kernel<<<dim3(N, 5), 224>>>(x);
    layer2_kernel<<<N, 512, SM2>>>();
    layer3_kernel<<<N, 160, SM3>>>(wo, bo, out);
}

// round 9
// speedup vs baseline: 3.3124x; 1.1629x over previous
#include <cuda_runtime.h>
#include <math.h>

#define EPS 1e-12f
typedef unsigned long long ull;

// ---- packed f32x2 helpers (each half = separately-rounded IEEE op) ---------
__device__ __forceinline__ ull pack2(float lo, float hi) {
    ull r; asm("mov.b64 %0, {%1,%2};" : "=l"(r) : "f"(lo), "f"(hi)); return r;
}
__device__ __forceinline__ void unpack2(ull p, float& lo, float& hi) {
    asm("mov.b64 {%0,%1}, %2;" : "=f"(lo), "=f"(hi) : "l"(p));
}
__device__ __forceinline__ ull ffma2(ull a, ull b, ull c) {
    ull d; asm("fma.rn.f32x2 %0, %1, %2, %3;" : "=l"(d) : "l"(a), "l"(b), "l"(c));
    return d;
}

// ---------------- persistent scratch ----------------------------------------
__device__ float  g_wn1[80 * 75];
__device__ float2 g_wn1d[80 * 75];    // duplicated (w,w) for FFMA2
__device__ float  g_e1[80];
__device__ float  g_wn2d[80 * 9];
__device__ float  g_e2d[80];
__device__ float  g_wn2p[40 * 80];
__device__ float2 g_wn2p2[40 * 80];   // duplicated (w,w)
__device__ float  g_e2p[40];
__device__ float  g_wn3[40 * 360];
__device__ float  g_e3[40];
__device__ float  g_qv[4];

__device__ float g_xn1[1024 * 784];           // layer1 patch-norm denominators
__device__ float g_buf1[1024 * 80 * 14 * 14]; // pooled layer1 g-output
__device__ float g_t2d[1024 * 80 * 144];      // depthwise g-output
__device__ float g_buf2[1024 * 40 * 6 * 6];   // pooled layer2 g-output

// g(y) = sign(y) * (|y|+EPS)^e
__device__ __forceinline__ float scs_g(float y, float e) {
    float a = __fadd_rn(fabsf(y), EPS);
    float r = powf(a, e);
    return (y > 0.f) ? r : ((y < 0.f) ? -r : 0.f);
}

__device__ __forceinline__ float maxabs4(float a, float b, float c, float d) {
    float pmx = fmaxf(fmaxf(a, b), fmaxf(c, d));
    float pmn = fminf(fminf(a, b), fminf(c, d));
    return (pmx >= -pmn) ? pmx : pmn;
}

// ---------------- weight prep (chains bit-identical to round 7) -------------
__global__ void prep_kernel(const float* w1, const float* p1, const float* q1,
                            const float* w2d, const float* p2d, const float* q2d,
                            const float* w2p, const float* p2p, const float* q2p,
                            const float* w3, const float* p3, const float* q3) {
    int b = blockIdx.x, t = threadIdx.x;
    const float *w, *p, *q;
    float *wn, *e;
    int n, c, li;
    if (b < 80)       { c = b;       w = w1  + c * 75;  n = 75;  wn = g_wn1  + c * 75;  p = p1;  q = q1;  e = g_e1;  li = 0; }
    else if (b < 160) { c = b - 80;  w = w2d + c * 9;   n = 9;   wn = g_wn2d + c * 9;   p = p2d; q = q2d; e = g_e2d; li = 1; }
    else if (b < 200) { c = b - 160; w = w2p + c * 80;  n = 80;  wn = g_wn2p + c * 80;  p = p2p; q = q2p; e = g_e2p; li = 2; }
    else              { c = b - 200; w = w3  + c * 360; n = 360; wn = g_wn3  + c * 360; p = p3;  q = q3;  e = g_e3;  li = 3; }
    float qt = __fdiv_rn(q[0], 100.0f);
    float qv = __fmul_rn(qt, qt);
    float s = 0.f;
    for (int i = t; i < n; i += 32) {
        float v = w[i];
        s = __fadd_rn(s, __fmul_rn(v, v));
    }
    #pragma unroll
    for (int o = 16; o > 0; o >>= 1)
        s = __fadd_rn(s, __shfl_down_sync(0xffffffffu, s, o));
    s = __shfl_sync(0xffffffffu, s, 0);
    float wnorm = __fadd_rn(sqrtf(__fadd_rn(s, EPS)), qv);
    for (int i = t; i < n; i += 32) {
        float v = __fdiv_rn(w[i], wnorm);
        wn[i] = v;
        if (li == 0) g_wn1d[c * 75 + i]  = make_float2(v, v);
        if (li == 2) g_wn2p2[c * 80 + i] = make_float2(v, v);
    }
    if (t == 0) {
        float pe = __fdiv_rn(p[c], 10.0f);
        e[c] = __fmul_rn(pe, pe);
        if (c == 0) g_qv[li] = qv;
    }
}

// ---------------- layer1 patch norms ((ky,kx,c) order) ----------------------
__global__ void xnorm1_kernel(const float* x) {
    __shared__ float sx[3072];
    int img = blockIdx.x;
    const float* xp = x + img * 3072;
    for (int i = threadIdx.x; i < 3072; i += 256) sx[i] = xp[i];
    __syncthreads();
    float qv = g_qv[0];
    for (int pos = threadIdx.x; pos < 784; pos += 256) {
        int oy = pos / 28, ox = pos % 28;
        float ss = 0.f;
        #pragma unroll
        for (int ky = 0; ky < 5; ky++)
            #pragma unroll
            for (int kx = 0; kx < 5; kx++)
                #pragma unroll
                for (int c = 0; c < 3; c++) {
                    float v = sx[c * 1024 + (oy + ky) * 32 + ox + kx];
                    ss = __fadd_rn(ss, __fmul_rn(v, v));
                }
        g_xn1[img * 784 + pos] = __fadd_rn(sqrtf(__fadd_rn(ss, EPS)), qv);
    }
}

// ---------------- layer1: conv 5x5 + pool + g, FFMA2-packed -----------------
// acc2[t][r*2+p] holds chains (j=r*4+2p, j=r*4+2p+1); every chain sees
// (ky,kx,c) in exact fmaf order.
__global__ void __launch_bounds__(224) conv1_kernel(const float* x) {
    __shared__ float sx[3072];
    __shared__ ull  sw2[16 * 75];
    __shared__ float sxn[784];
    __shared__ float se[16];
    int img = blockIdx.x;
    int cb = blockIdx.y * 16;
    const float* xp = x + img * 3072;
    const ull* wsrc = reinterpret_cast<const ull*>(g_wn1d) + cb * 75;
    for (int i = threadIdx.x; i < 3072; i += 224) sx[i] = xp[i];
    for (int i = threadIdx.x; i < 1200; i += 224) sw2[i] = wsrc[i];
    for (int i = threadIdx.x; i < 784; i += 224) sxn[i] = g_xn1[img * 784 + i];
    if (threadIdx.x < 16) se[threadIdx.x] = g_e1[cb + threadIdx.x];
    __syncthreads();
    int tid = threadIdx.x;
    if (tid >= 196) return;
    int ct = tid / 98, pp = tid % 98;
    int py = pp / 7;
    int pq = pp % 7;
    int cx0 = 4 * pq;

    ull acc2[8][4];
    #pragma unroll
    for (int a = 0; a < 8; a++)
        #pragma unroll
        for (int b2 = 0; b2 < 4; b2++) acc2[a][b2] = 0ull;

    #pragma unroll 1
    for (int ky = 0; ky < 5; ky++) {
        const float* xr = &sx[(2 * py + ky) * 32 + cx0];
        #pragma unroll
        for (int kx = 0; kx < 5; kx++) {
            #pragma unroll
            for (int c = 0; c < 3; c++) {
                ull xp2[4];
                #pragma unroll
                for (int r = 0; r < 2; r++) {
                    const float* xc = xr + c * 1024 + r * 32 + kx;
                    xp2[r * 2 + 0] = pack2(xc[0], xc[1]);
                    xp2[r * 2 + 1] = pack2(xc[2], xc[3]);
                }
                int widx = c * 25 + ky * 5 + kx;
                #pragma unroll
                for (int t = 0; t < 8; t++) {
                    ull w2 = sw2[(ct * 8 + t) * 75 + widx];
                    #pragma unroll
                    for (int pr = 0; pr < 4; pr++)
                        acc2[t][pr] = ffma2(w2, xp2[pr], acc2[t][pr]);
                }
            }
        }
    }
    float xnv[8];
    #pragma unroll
    for (int r = 0; r < 2; r++)
        #pragma unroll
        for (int cl = 0; cl < 4; cl++)
            xnv[r * 4 + cl] = sxn[(2 * py + r) * 28 + cx0 + cl];

    int ob = ((img * 80 + cb + ct * 8) * 14 + py) * 14 + 2 * pq;
    #pragma unroll
    for (int t = 0; t < 8; t++) {
        float y[8];
        #pragma unroll
        for (int r = 0; r < 2; r++)
            #pragma unroll
            for (int p = 0; p < 2; p++)
                unpack2(acc2[t][r * 2 + p], y[r * 4 + 2 * p], y[r * 4 + 2 * p + 1]);
        #pragma unroll
        for (int j = 0; j < 8; j++) y[j] = __fdiv_rn(y[j], xnv[j]);
        float e = se[ct * 8 + t];
        g_buf1[ob + t * 196]     = scs_g(maxabs4(y[0], y[1], y[4], y[5]), e);
        g_buf1[ob + t * 196 + 1] = scs_g(maxabs4(y[2], y[3], y[6], y[7]), e);
    }
}

// ---------------- layer2a: depthwise 3x3 + g (global in/out) ----------------
__global__ void __launch_bounds__(256) k2d_kernel() {
    int img = blockIdx.x, tid = threadIdx.x;
    float qv2d = g_qv[1];
    for (int tile = tid; tile < 960; tile += 256) {
        int ch = tile / 12, oy = tile % 12;
        const float* wp = g_wn2d + ch * 9;
        float wreg[9];
        #pragma unroll
        for (int k = 0; k < 9; k++) wreg[k] = wp[k];
        float e = g_e2d[ch];
        const float* xr = g_buf1 + (img * 80 + ch) * 196 + oy * 14;
        float rw[3][14];
        #pragma unroll
        for (int rr = 0; rr < 3; rr++)
            #pragma unroll
            for (int j = 0; j < 14; j++) rw[rr][j] = __ldg(&xr[rr * 14 + j]);
        float* op = g_t2d + (img * 80 + ch) * 144 + oy * 12;
        #pragma unroll
        for (int ox = 0; ox < 12; ox++) {
            float num = 0.f, ss = 0.f;
            #pragma unroll
            for (int ky = 0; ky < 3; ky++)
                #pragma unroll
                for (int kx = 0; kx < 3; kx++) {
                    float v = rw[ky][ox + kx];
                    num = fmaf(wreg[ky * 3 + kx], v, num);
                    ss  = __fadd_rn(ss, __fmul_rn(v, v));
                }
            float y = __fdiv_rn(num, __fadd_rn(sqrtf(__fadd_rn(ss, EPS)), qv2d));
            op[ox] = scs_g(y, e);
        }
    }
}

// ---------------- layer2b: pointwise 1x1 (FFMA2) + pool + g -----------------
__global__ void __launch_bounds__(384) k2p_kernel() {
    extern __shared__ char smc[];
    float* s_t2d = (float*)smc;                       // 11520 f = 46080 B
    ull*  s_w2   = (ull*)(smc + 46080);               // 3200 ull = 25600 B
    float* s_xn  = (float*)(smc + 46080 + 25600);     // 144 f
    float* s_e2p = s_xn + 144;                        // 40 f
    int img = blockIdx.x, tid = threadIdx.x;

    const float4* src = (const float4*)(g_t2d + img * 11520);
    for (int i = tid; i < 2880; i += 384) ((float4*)s_t2d)[i] = src[i];
    const ull* wsrc = reinterpret_cast<const ull*>(g_wn2p2);
    for (int i = tid; i < 3200; i += 384) s_w2[i] = wsrc[i];
    if (tid < 40) s_e2p[tid] = g_e2p[tid];
    __syncthreads();
    float qv2p = g_qv[2];

    // per-pixel channel-norm denominators (k-sequential)
    for (int pix = tid; pix < 144; pix += 384) {
        float ss = 0.f;
        for (int k = 0; k < 80; k++) {
            float v = s_t2d[k * 144 + pix];
            ss = __fadd_rn(ss, __fmul_rn(v, v));
        }
        s_xn[pix] = __fadd_rn(sqrtf(__fadd_rn(ss, EPS)), qv2p);
    }
    __syncthreads();

    if (tid < 360) {
        int cg = tid / 36, quad = tid % 36;
        int qy = quad / 6, qx = quad % 6;
        int p00 = (2 * qy) * 12 + 2 * qx;
        int p01 = p00 + 1, p10 = p00 + 12, p11 = p00 + 13;
        ull acc2[4][2];
        #pragma unroll
        for (int i = 0; i < 4; i++) { acc2[i][0] = 0ull; acc2[i][1] = 0ull; }
        for (int k = 0; k < 80; k++) {
            ull xa = pack2(s_t2d[k * 144 + p00], s_t2d[k * 144 + p01]);
            ull xb = pack2(s_t2d[k * 144 + p10], s_t2d[k * 144 + p11]);
            #pragma unroll
            for (int i = 0; i < 4; i++) {
                ull w2 = s_w2[(cg * 4 + i) * 80 + k];
                acc2[i][0] = ffma2(w2, xa, acc2[i][0]);
                acc2[i][1] = ffma2(w2, xb, acc2[i][1]);
            }
        }
        float n0 = s_xn[p00], n1 = s_xn[p01], n2 = s_xn[p10], n3 = s_xn[p11];
        #pragma unroll
        for (int i = 0; i < 4; i++) {
            float a0, a1, a2, a3;
            unpack2(acc2[i][0], a0, a1);
            unpack2(acc2[i][1], a2, a3);
            float y0 = __fdiv_rn(a0, n0);
            float y1 = __fdiv_rn(a1, n1);
            float y2 = __fdiv_rn(a2, n2);
            float y3 = __fdiv_rn(a3, n3);
            float v = maxabs4(y0, y1, y2, y3);
            int co = cg * 4 + i;
            g_buf2[((img * 40 + co) * 6 + qy) * 6 + qx] = scs_g(v, s_e2p[co]);
        }
    }
}

// ---------------- layer3: conv 3x3 (40->40) + pool 4x4 + g + FC -------------
__global__ void __launch_bounds__(160) layer3_kernel(const float* wo, const float* bo, float* out) {
    extern __shared__ float sm[];
    float* s_in   = sm;              // 1440
    float* s_w3   = sm + 1440;       // 14400
    float* s_wo   = s_w3 + 14400;    // 400
    float* s_e3   = s_wo + 400;      // 40
    float* s_xn   = s_e3 + 40;       // 16
    float* s_qmax = s_xn + 16;       // 160
    float* s_qmin = s_qmax + 160;    // 160
    float* s_vec  = s_qmin + 160;    // 40
    float* s_bo   = s_vec + 40;      // 16
    int img = blockIdx.x, tid = threadIdx.x;

    const float4* src = (const float4*)(g_buf2 + img * 1440);
    for (int i = tid; i < 360; i += 160) ((float4*)s_in)[i] = src[i];
    for (int i = tid; i < 3600; i += 160) ((float4*)s_w3)[i] = ((const float4*)g_wn3)[i];
    for (int i = tid; i < 400; i += 160) s_wo[i] = wo[i];
    if (tid < 40) s_e3[tid] = g_e3[tid];
    if (tid < 10) s_bo[tid] = bo[tid];
    __syncthreads();
    float qv3 = g_qv[3];

    if (tid < 16) {
        int oy = tid / 4, ox = tid % 4;
        float ss = 0.f;
        #pragma unroll
        for (int ky = 0; ky < 3; ky++)
            #pragma unroll
            for (int kx = 0; kx < 3; kx++)
                for (int c = 0; c < 40; c++) {
                    float v = s_in[c * 36 + (oy + ky) * 6 + ox + kx];
                    ss = __fadd_rn(ss, __fmul_rn(v, v));
                }
        s_xn[tid] = __fadd_rn(sqrtf(__fadd_rn(ss, EPS)), qv3);
    }
    __syncthreads();

    {
        int co = tid >> 2, quad = tid & 3;
        int qy = quad >> 1, qx = quad & 1;
        float acc[4] = {0.f, 0.f, 0.f, 0.f};
        #pragma unroll
        for (int ky = 0; ky < 3; ky++)
            #pragma unroll
            for (int kx = 0; kx < 3; kx++)
                for (int c = 0; c < 40; c++) {
                    float w = s_w3[(co * 40 + c) * 9 + ky * 3 + kx];
                    const float* ip = &s_in[c * 36];
                    acc[0] = fmaf(w, ip[(2 * qy + ky) * 6 + 2 * qx + kx], acc[0]);
                    acc[1] = fmaf(w, ip[(2 * qy + ky) * 6 + 2 * qx + 1 + kx], acc[1]);
                    acc[2] = fmaf(w, ip[(2 * qy + 1 + ky) * 6 + 2 * qx + kx], acc[2]);
                    acc[3] = fmaf(w, ip[(2 * qy + 1 + ky) * 6 + 2 * qx + 1 + kx], acc[3]);
                }
        float y0 = __fdiv_rn(acc[0], s_xn[(2 * qy) * 4 + 2 * qx]);
        float y1 = __fdiv_rn(acc[1], s_xn[(2 * qy) * 4 + 2 * qx + 1]);
        float y2 = __fdiv_rn(acc[2], s_xn[(2 * qy + 1) * 4 + 2 * qx]);
        float y3 = __fdiv_rn(acc[3], s_xn[(2 * qy + 1) * 4 + 2 * qx + 1]);
        s_qmax[tid] = fmaxf(fmaxf(y0, y1), fmaxf(y2, y3));
        s_qmin[tid] = fminf(fminf(y0, y1), fminf(y2, y3));
    }
    __syncthreads();
    if (tid < 40) {
        float pmx = fmaxf(fmaxf(s_qmax[tid * 4], s_qmax[tid * 4 + 1]),
                          fmaxf(s_qmax[tid * 4 + 2], s_qmax[tid * 4 + 3]));
        float pmn = fminf(fminf(s_qmin[tid * 4], s_qmin[tid * 4 + 1]),
                          fminf(s_qmin[tid * 4 + 2], s_qmin[tid * 4 + 3]));
        float v = (pmx >= -pmn) ? pmx : pmn;
        s_vec[tid] = scs_g(v, s_e3[tid]);
    }
    __syncthreads();
    if (tid < 10) {
        float s = 0.f;
        #pragma unroll 1
        for (int c = 0; c < 40; c++) s = fmaf(s_vec[c], s_wo[tid * 40 + c], s);
        out[img * 10 + tid] = __fadd_rn(s, s_bo[tid]);
    }
}

// ---------------- launch ------------------------------------------------------
extern "C" void kernel_launch(void* const* d_in, const int* in_sizes, int n_in,
                              void* d_out, int out_size) {
    const float* x   = (const float*)d_in[0];
    const float* w1  = (const float*)d_in[1];
    const float* p1  = (const float*)d_in[2];
    const float* q1  = (const float*)d_in[3];
    const float* w2d = (const float*)d_in[4];
    const float* p2d = (const float*)d_in[5];
    const float* q2d = (const float*)d_in[6];
    const float* w2p = (const float*)d_in[7];
    const float* p2p = (const float*)d_in[8];
    const float* q2p = (const float*)d_in[9];
    const float* w3  = (const float*)d_in[10];
    const float* p3  = (const float*)d_in[11];
    const float* q3  = (const float*)d_in[12];
    const float* wo  = (const float*)d_in[13];
    const float* bo  = (const float*)d_in[14];
    float* out = (float*)d_out;

    int N = in_sizes[0] / 3072;

    static const size_t SM2P = 46080 + 25600 + 144 * 4 + 40 * 4 + 64;
    static const size_t SM3 = (1440 + 14400 + 400 + 40 + 16 + 160 + 160 + 40 + 16) * sizeof(float);
    cudaFuncSetAttribute(k2p_kernel, cudaFuncAttributeMaxDynamicSharedMemorySize, (int)SM2P);
    cudaFuncSetAttribute(layer3_kernel, cudaFuncAttributeMaxDynamicSharedMemorySize, (int)SM3);

    prep_kernel<<<240, 32>>>(w1, p1, q1, w2d, p2d, q2d, w2p, p2p, q2p, w3, p3, q3);
    xnorm1_kernel<<<N, 256>>>(x);
    conv1_kernel<<<dim3(N, 5), 224>>>(x);
    k2d_kernel<<<N, 256>>>();
    k2p_kernel<<<N, 384, SM2P>>>();
    layer3_kernel<<<N, 160, SM3>>>(wo, bo, out);
}

// round 10
// speedup vs baseline: 3.9227x; 1.1842x over previous
#include <cuda_runtime.h>
#include <math.h>

#define EPS 1e-12f
typedef unsigned long long ull;

// ---- packed f32x2 helpers (each half = separately-rounded IEEE op) ---------
__device__ __forceinline__ ull pack2(float lo, float hi) {
    ull r; asm("mov.b64 %0, {%1,%2};" : "=l"(r) : "f"(lo), "f"(hi)); return r;
}
__device__ __forceinline__ void unpack2(ull p, float& lo, float& hi) {
    asm("mov.b64 {%0,%1}, %2;" : "=f"(lo), "=f"(hi) : "l"(p));
}
__device__ __forceinline__ ull ffma2(ull a, ull b, ull c) {
    ull d; asm("fma.rn.f32x2 %0, %1, %2, %3;" : "=l"(d) : "l"(a), "l"(b), "l"(c));
    return d;
}

// ---------------- persistent scratch ----------------------------------------
__device__ ull    g_wn1p[40 * 75];    // channel-pair packed conv1 weights
__device__ float  g_e1[80];
__device__ float  g_wn2d[80 * 9];
__device__ float  g_e2d[80];
__device__ float2 g_wn2p2[40 * 80];   // duplicated (w,w) pointwise weights
__device__ float  g_e2p[40];
__device__ float  g_wn3[40 * 360];
__device__ float  g_e3[40];
__device__ float  g_qv[4];

__device__ float g_xn1[1024 * 784];           // layer1 patch-norm denominators
__device__ float g_buf1[1024 * 80 * 14 * 14]; // pooled layer1 g-output
__device__ float g_buf2[1024 * 40 * 6 * 6];   // pooled layer2 g-output

// g(y) = sign(y) * (|y|+EPS)^e
__device__ __forceinline__ float scs_g(float y, float e) {
    float a = __fadd_rn(fabsf(y), EPS);
    float r = powf(a, e);
    return (y > 0.f) ? r : ((y < 0.f) ? -r : 0.f);
}

__device__ __forceinline__ float maxabs4(float a, float b, float c, float d) {
    float pmx = fmaxf(fmaxf(a, b), fmaxf(c, d));
    float pmn = fminf(fminf(a, b), fminf(c, d));
    return (pmx >= -pmn) ? pmx : pmn;
}

// ---------------- weight prep (chains bit-identical) ------------------------
__global__ void prep_kernel(const float* w1, const float* p1, const float* q1,
                            const float* w2d, const float* p2d, const float* q2d,
                            const float* w2p, const float* p2p, const float* q2p,
                            const float* w3, const float* p3, const float* q3) {
    int b = blockIdx.x, t = threadIdx.x;
    const float *w, *p, *q;
    float *wn, *e;
    int n, c, li;
    if (b < 80)       { c = b;       w = w1  + c * 75;  n = 75;  wn = 0;               p = p1;  q = q1;  e = g_e1;  li = 0; }
    else if (b < 160) { c = b - 80;  w = w2d + c * 9;   n = 9;   wn = g_wn2d + c * 9;  p = p2d; q = q2d; e = g_e2d; li = 1; }
    else if (b < 200) { c = b - 160; w = w2p + c * 80;  n = 80;  wn = 0;               p = p2p; q = q2p; e = g_e2p; li = 2; }
    else              { c = b - 200; w = w3  + c * 360; n = 360; wn = g_wn3 + c * 360; p = p3;  q = q3;  e = g_e3;  li = 3; }
    float qt = __fdiv_rn(q[0], 100.0f);
    float qv = __fmul_rn(qt, qt);
    float s = 0.f;
    for (int i = t; i < n; i += 32) {
        float v = w[i];
        s = __fadd_rn(s, __fmul_rn(v, v));
    }
    #pragma unroll
    for (int o = 16; o > 0; o >>= 1)
        s = __fadd_rn(s, __shfl_down_sync(0xffffffffu, s, o));
    s = __shfl_sync(0xffffffffu, s, 0);
    float wnorm = __fadd_rn(sqrtf(__fadd_rn(s, EPS)), qv);
    for (int i = t; i < n; i += 32) {
        float v = __fdiv_rn(w[i], wnorm);
        if (li == 0) {
            // channel-pair layout: pair op=c/2, half=(c&1)
            ((float*)g_wn1p)[(c >> 1) * 150 + 2 * i + (c & 1)] = v;
        } else if (li == 2) {
            g_wn2p2[c * 80 + i] = make_float2(v, v);
        } else {
            wn[i] = v;
        }
    }
    if (t == 0) {
        float pe = __fdiv_rn(p[c], 10.0f);
        e[c] = __fmul_rn(pe, pe);
        if (c == 0) g_qv[li] = qv;
    }
}

// ---------------- layer1 patch norms ((ky,kx,c) order) ----------------------
__global__ void xnorm1_kernel(const float* x) {
    __shared__ float sx[3072];
    int img = blockIdx.x;
    const float* xp = x + img * 3072;
    for (int i = threadIdx.x; i < 3072; i += 256) sx[i] = xp[i];
    __syncthreads();
    float qv = g_qv[0];
    for (int pos = threadIdx.x; pos < 784; pos += 256) {
        int oy = pos / 28, ox = pos % 28;
        float ss = 0.f;
        #pragma unroll
        for (int ky = 0; ky < 5; ky++)
            #pragma unroll
            for (int kx = 0; kx < 5; kx++)
                #pragma unroll
                for (int c = 0; c < 3; c++) {
                    float v = sx[c * 1024 + (oy + ky) * 32 + ox + kx];
                    ss = __fadd_rn(ss, __fmul_rn(v, v));
                }
        g_xn1[img * 784 + pos] = __fadd_rn(sqrtf(__fadd_rn(ss, EPS)), qv);
    }
}

// ---------------- layer1: conv 5x5 + pool + g, channel-pair FFMA2 -----------
// acc2[t2][j]: halves = out-channels (2*t2, 2*t2+1) at conv position j;
// each chain sees (c, ky, kx) sequentially (round-8-validated order).
__global__ void __launch_bounds__(196) conv1_kernel(const float* x) {
    __shared__ float sx[3072];
    __shared__ ull   sw2[600];      // 8 channel-pairs x 75
    __shared__ float sxn[784];
    __shared__ float se[16];
    int img = blockIdx.x;
    int cb = blockIdx.y * 16;
    int tid = threadIdx.x;
    const float* xp = x + img * 3072;
    const ull* wsrc = g_wn1p + (cb >> 1) * 75;
    for (int i = tid; i < 3072; i += 196) sx[i] = xp[i];
    for (int i = tid; i < 600; i += 196) sw2[i] = wsrc[i];
    for (int i = tid; i < 784; i += 196) sxn[i] = g_xn1[img * 784 + i];
    if (tid < 16) se[tid] = g_e1[cb + tid];
    __syncthreads();

    int ct = tid / 98, pp = tid % 98;
    int py = pp / 7;          // pooled row 0..13
    int pq = pp % 7;          // pooled col pair 0..6
    int cx0 = 4 * pq;

    ull acc2[4][8];
    #pragma unroll
    for (int a = 0; a < 4; a++)
        #pragma unroll
        for (int j = 0; j < 8; j++) acc2[a][j] = 0ull;

    #pragma unroll 1
    for (int c = 0; c < 3; c++) {
        float xw[6][8];
        #pragma unroll
        for (int i = 0; i < 6; i++)
            #pragma unroll
            for (int j = 0; j < 8; j++)
                xw[i][j] = sx[c * 1024 + (2 * py + i) * 32 + cx0 + j];
        #pragma unroll
        for (int ky = 0; ky < 5; ky++)
            #pragma unroll
            for (int kx = 0; kx < 5; kx++) {
                ull xp2[8];
                #pragma unroll
                for (int r = 0; r < 2; r++)
                    #pragma unroll
                    for (int cl = 0; cl < 4; cl++) {
                        float v = xw[ky + r][kx + cl];
                        xp2[r * 4 + cl] = pack2(v, v);
                    }
                int widx = c * 25 + ky * 5 + kx;
                #pragma unroll
                for (int t2 = 0; t2 < 4; t2++) {
                    ull w2 = sw2[(ct * 4 + t2) * 75 + widx];
                    #pragma unroll
                    for (int j = 0; j < 8; j++)
                        acc2[t2][j] = ffma2(w2, xp2[j], acc2[t2][j]);
                }
            }
    }

    float xnv[8];
    #pragma unroll
    for (int r = 0; r < 2; r++)
        #pragma unroll
        for (int cl = 0; cl < 4; cl++)
            xnv[r * 4 + cl] = sxn[(2 * py + r) * 28 + cx0 + cl];

    int obase = ((img * 80 + cb + ct * 8) * 14 + py) * 14 + 2 * pq;
    #pragma unroll
    for (int t2 = 0; t2 < 4; t2++) {
        float ya[8], yb[8];
        #pragma unroll
        for (int j = 0; j < 8; j++) unpack2(acc2[t2][j], ya[j], yb[j]);
        #pragma unroll
        for (int j = 0; j < 8; j++) {
            ya[j] = __fdiv_rn(ya[j], xnv[j]);
            yb[j] = __fdiv_rn(yb[j], xnv[j]);
        }
        float e0 = se[ct * 8 + 2 * t2];
        float e1 = se[ct * 8 + 2 * t2 + 1];
        int o0 = obase + (2 * t2) * 196;
        int o1 = o0 + 196;
        g_buf1[o0]     = scs_g(maxabs4(ya[0], ya[1], ya[4], ya[5]), e0);
        g_buf1[o0 + 1] = scs_g(maxabs4(ya[2], ya[3], ya[6], ya[7]), e0);
        g_buf1[o1]     = scs_g(maxabs4(yb[0], yb[1], yb[4], yb[5]), e1);
        g_buf1[o1 + 1] = scs_g(maxabs4(yb[2], yb[3], yb[6], yb[7]), e1);
    }
}

// ---------------- layer2 merged: depthwise + pointwise + pool + g -----------
__global__ void __launch_bounds__(384) k2_kernel() {
    extern __shared__ char smc[];
    float* s_t2d = (float*)smc;                       // 11520 f = 46080 B
    ull*   s_w2  = (ull*)(smc + 46080);               // 3200 ull = 25600 B
    float* s_xn  = (float*)(smc + 46080 + 25600);     // 144 f
    float* s_e2p = s_xn + 144;                        // 40 f
    int img = blockIdx.x, tid = threadIdx.x;

    const ull* wsrc = reinterpret_cast<const ull*>(g_wn2p2);
    for (int i = tid; i < 3200; i += 384) s_w2[i] = wsrc[i];
    if (tid < 40) s_e2p[tid] = g_e2p[tid];
    float qv2d = g_qv[1], qv2p = g_qv[2];

    // phase A: depthwise 3x3 + g -> smem (chains identical to k2d)
    for (int tile = tid; tile < 960; tile += 384) {
        int ch = tile / 12, oy = tile % 12;
        const float* wp = g_wn2d + ch * 9;
        float wreg[9];
        #pragma unroll
        for (int k = 0; k < 9; k++) wreg[k] = wp[k];
        float e = g_e2d[ch];
        const float* xr = g_buf1 + (img * 80 + ch) * 196 + oy * 14;
        float rw[3][14];
        #pragma unroll
        for (int rr = 0; rr < 3; rr++)
            #pragma unroll
            for (int j = 0; j < 14; j++) rw[rr][j] = __ldg(&xr[rr * 14 + j]);
        float* op = s_t2d + ch * 144 + oy * 12;
        #pragma unroll
        for (int ox = 0; ox < 12; ox++) {
            float num = 0.f, ss = 0.f;
            #pragma unroll
            for (int ky = 0; ky < 3; ky++)
                #pragma unroll
                for (int kx = 0; kx < 3; kx++) {
                    float v = rw[ky][ox + kx];
                    num = fmaf(wreg[ky * 3 + kx], v, num);
                    ss  = __fadd_rn(ss, __fmul_rn(v, v));
                }
            float y = __fdiv_rn(num, __fadd_rn(sqrtf(__fadd_rn(ss, EPS)), qv2d));
            op[ox] = scs_g(y, e);
        }
    }
    __syncthreads();

    // phase B1: per-pixel channel-norm denominators (k-sequential)
    for (int pix = tid; pix < 144; pix += 384) {
        float ss = 0.f;
        for (int k = 0; k < 80; k++) {
            float v = s_t2d[k * 144 + pix];
            ss = __fadd_rn(ss, __fmul_rn(v, v));
        }
        s_xn[pix] = __fadd_rn(sqrtf(__fadd_rn(ss, EPS)), qv2p);
    }
    __syncthreads();

    // phase B2: pointwise (FFMA2 position pairs) + pool 2x2 + g
    if (tid < 360) {
        int cg = tid / 36, quad = tid % 36;
        int qy = quad / 6, qx = quad % 6;
        int p00 = (2 * qy) * 12 + 2 * qx;
        int p01 = p00 + 1, p10 = p00 + 12, p11 = p00 + 13;
        ull acc2[4][2];
        #pragma unroll
        for (int i = 0; i < 4; i++) { acc2[i][0] = 0ull; acc2[i][1] = 0ull; }
        for (int k = 0; k < 80; k++) {
            ull xa = pack2(s_t2d[k * 144 + p00], s_t2d[k * 144 + p01]);
            ull xb = pack2(s_t2d[k * 144 + p10], s_t2d[k * 144 + p11]);
            #pragma unroll
            for (int i = 0; i < 4; i++) {
                ull w2 = s_w2[(cg * 4 + i) * 80 + k];
                acc2[i][0] = ffma2(w2, xa, acc2[i][0]);
                acc2[i][1] = ffma2(w2, xb, acc2[i][1]);
            }
        }
        float n0 = s_xn[p00], n1 = s_xn[p01], n2 = s_xn[p10], n3 = s_xn[p11];
        #pragma unroll
        for (int i = 0; i < 4; i++) {
            float a0, a1, a2, a3;
            unpack2(acc2[i][0], a0, a1);
            unpack2(acc2[i][1], a2, a3);
            float y0 = __fdiv_rn(a0, n0);
            float y1 = __fdiv_rn(a1, n1);
            float y2 = __fdiv_rn(a2, n2);
            float y3 = __fdiv_rn(a3, n3);
            float v = maxabs4(y0, y1, y2, y3);
            int co = cg * 4 + i;
            g_buf2[((img * 40 + co) * 6 + qy) * 6 + qx] = scs_g(v, s_e2p[co]);
        }
    }
}

// ---------------- layer3: conv 3x3 (40->40) + pool 4x4 + g + FC -------------
__global__ void __launch_bounds__(160) layer3_kernel(const float* wo, const float* bo, float* out) {
    extern __shared__ float sm[];
    float* s_in   = sm;              // 1440
    float* s_w3   = sm + 1440;       // 14400
    float* s_wo   = s_w3 + 14400;    // 400
    float* s_e3   = s_wo + 400;      // 40
    float* s_xn   = s_e3 + 40;       // 16
    float* s_qmax = s_xn + 16;       // 160
    float* s_qmin = s_qmax + 160;    // 160
    float* s_vec  = s_qmin + 160;    // 40
    float* s_bo   = s_vec + 40;      // 16
    int img = blockIdx.x, tid = threadIdx.x;

    const float4* src = (const float4*)(g_buf2 + img * 1440);
    for (int i = tid; i < 360; i += 160) ((float4*)s_in)[i] = src[i];
    for (int i = tid; i < 3600; i += 160) ((float4*)s_w3)[i] = ((const float4*)g_wn3)[i];
    for (int i = tid; i < 400; i += 160) s_wo[i] = wo[i];
    if (tid < 40) s_e3[tid] = g_e3[tid];
    if (tid < 10) s_bo[tid] = bo[tid];
    __syncthreads();
    float qv3 = g_qv[3];

    if (tid < 16) {
        int oy = tid / 4, ox = tid % 4;
        float ss = 0.f;
        #pragma unroll
        for (int ky = 0; ky < 3; ky++)
            #pragma unroll
            for (int kx = 0; kx < 3; kx++)
                for (int c = 0; c < 40; c++) {
                    float v = s_in[c * 36 + (oy + ky) * 6 + ox + kx];
                    ss = __fadd_rn(ss, __fmul_rn(v, v));
                }
        s_xn[tid] = __fadd_rn(sqrtf(__fadd_rn(ss, EPS)), qv3);
    }
    __syncthreads();

    {
        int co = tid >> 2, quad = tid & 3;
        int qy = quad >> 1, qx = quad & 1;
        float acc[4] = {0.f, 0.f, 0.f, 0.f};
        #pragma unroll
        for (int ky = 0; ky < 3; ky++)
            #pragma unroll
            for (int kx = 0; kx < 3; kx++)
                for (int c = 0; c < 40; c++) {
                    float w = s_w3[(co * 40 + c) * 9 + ky * 3 + kx];
                    const float* ip = &s_in[c * 36];
                    acc[0] = fmaf(w, ip[(2 * qy + ky) * 6 + 2 * qx + kx], acc[0]);
                    acc[1] = fmaf(w, ip[(2 * qy + ky) * 6 + 2 * qx + 1 + kx], acc[1]);
                    acc[2] = fmaf(w, ip[(2 * qy + 1 + ky) * 6 + 2 * qx + kx], acc[2]);
                    acc[3] = fmaf(w, ip[(2 * qy + 1 + ky) * 6 + 2 * qx + 1 + kx], acc[3]);
                }
        float y0 = __fdiv_rn(acc[0], s_xn[(2 * qy) * 4 + 2 * qx]);
        float y1 = __fdiv_rn(acc[1], s_xn[(2 * qy) * 4 + 2 * qx + 1]);
        float y2 = __fdiv_rn(acc[2], s_xn[(2 * qy + 1) * 4 + 2 * qx]);
        float y3 = __fdiv_rn(acc[3], s_xn[(2 * qy + 1) * 4 + 2 * qx + 1]);
        s_qmax[tid] = fmaxf(fmaxf(y0, y1), fmaxf(y2, y3));
        s_qmin[tid] = fminf(fminf(y0, y1), fminf(y2, y3));
    }
    __syncthreads();
    if (tid < 40) {
        float pmx = fmaxf(fmaxf(s_qmax[tid * 4], s_qmax[tid * 4 + 1]),
                          fmaxf(s_qmax[tid * 4 + 2], s_qmax[tid * 4 + 3]));
        float pmn = fminf(fminf(s_qmin[tid * 4], s_qmin[tid * 4 + 1]),
                          fminf(s_qmin[tid * 4 + 2], s_qmin[tid * 4 + 3]));
        float v = (pmx >= -pmn) ? pmx : pmn;
        s_vec[tid] = scs_g(v, s_e3[tid]);
    }
    __syncthreads();
    if (tid < 10) {
        float s = 0.f;
        #pragma unroll 1
        for (int c = 0; c < 40; c++) s = fmaf(s_vec[c], s_wo[tid * 40 + c], s);
        out[img * 10 + tid] = __fadd_rn(s, s_bo[tid]);
    }
}

// ---------------- launch ------------------------------------------------------
extern "C" void kernel_launch(void* const* d_in, const int* in_sizes, int n_in,
                              void* d_out, int out_size) {
    const float* x   = (const float*)d_in[0];
    const float* w1  = (const float*)d_in[1];
    const float* p1  = (const float*)d_in[2];
    const float* q1  = (const float*)d_in[3];
    const float* w2d = (const float*)d_in[4];
    const float* p2d = (const float*)d_in[5];
    const float* q2d = (const float*)d_in[6];
    const float* w2p = (const float*)d_in[7];
    const float* p2p = (const float*)d_in[8];
    const float* q2p = (const float*)d_in[9];
    const float* w3  = (const float*)d_in[10];
    const float* p3  = (const float*)d_in[11];
    const float* q3  = (const float*)d_in[12];
    const float* wo  = (const float*)d_in[13];
    const float* bo  = (const float*)d_in[14];
    float* out = (float*)d_out;

    int N = in_sizes[0] / 3072;

    static const size_t SM2 = 46080 + 25600 + 144 * 4 + 40 * 4 + 64;
    static const size_t SM3 = (1440 + 14400 + 400 + 40 + 16 + 160 + 160 + 40 + 16) * sizeof(float);
    cudaFuncSetAttribute(k2_kernel, cudaFuncAttributeMaxDynamicSharedMemorySize, (int)SM2);
    cudaFuncSetAttribute(layer3_kernel, cudaFuncAttributeMaxDynamicSharedMemorySize, (int)SM3);

    prep_kernel<<<240, 32>>>(w1, p1, q1, w2d, p2d, q2d, w2p, p2p, q2p, w3, p3, q3);
    xnorm1_kernel<<<N, 256>>>(x);
    conv1_kernel<<<dim3(N, 5), 196>>>(x);
    k2_kernel<<<N, 384, SM2>>>();
    layer3_kernel<<<N, 160, SM3>>>(wo, bo, out);
}

// round 11
// speedup vs baseline: 4.3977x; 1.1211x over previous
#include <cuda_runtime.h>
#include <math.h>

#define EPS 1e-12f
typedef unsigned long long ull;

// ---- packed f32x2 helpers (each half = separately-rounded IEEE op) ---------
__device__ __forceinline__ ull pack2(float lo, float hi) {
    ull r; asm("mov.b64 %0, {%1,%2};" : "=l"(r) : "f"(lo), "f"(hi)); return r;
}
__device__ __forceinline__ void unpack2(ull p, float& lo, float& hi) {
    asm("mov.b64 {%0,%1}, %2;" : "=f"(lo), "=f"(hi) : "l"(p));
}
__device__ __forceinline__ ull ffma2(ull a, ull b, ull c) {
    ull d; asm("fma.rn.f32x2 %0, %1, %2, %3;" : "=l"(d) : "l"(a), "l"(b), "l"(c));
    return d;
}

// ---------------- persistent scratch ----------------------------------------
__device__ ull    g_wn1p[40 * 75];    // conv1 weights, channel-pair packed
__device__ float  g_e1[80];
__device__ float  g_wn2d[80 * 9];
__device__ float  g_e2d[80];
__device__ ull    g_wn2pp[20 * 80];   // pointwise weights, channel-pair packed
__device__ float  g_e2p[40];
__device__ float  g_wn3[40 * 360];
__device__ float  g_e3[40];
__device__ float  g_qv[4];

__device__ float g_xn1[1024 * 784];           // layer1 patch-norm denominators
__device__ float g_buf1[1024 * 80 * 14 * 14]; // pooled layer1 g-output
__device__ float g_buf2[1024 * 40 * 6 * 6];   // pooled layer2 g-output

// g(y) = sign(y) * (|y|+EPS)^e
__device__ __forceinline__ float scs_g(float y, float e) {
    float a = __fadd_rn(fabsf(y), EPS);
    float r = powf(a, e);
    return (y > 0.f) ? r : ((y < 0.f) ? -r : 0.f);
}

__device__ __forceinline__ float maxabs4(float a, float b, float c, float d) {
    float pmx = fmaxf(fmaxf(a, b), fmaxf(c, d));
    float pmn = fminf(fminf(a, b), fminf(c, d));
    return (pmx >= -pmn) ? pmx : pmn;
}

// ---------------- weight prep (chains bit-identical) ------------------------
__global__ void prep_kernel(const float* w1, const float* p1, const float* q1,
                            const float* w2d, const float* p2d, const float* q2d,
                            const float* w2p, const float* p2p, const float* q2p,
                            const float* w3, const float* p3, const float* q3) {
    int b = blockIdx.x, t = threadIdx.x;
    const float *w, *p, *q;
    float *wn, *e;
    int n, c, li;
    if (b < 80)       { c = b;       w = w1  + c * 75;  n = 75;  wn = 0;               p = p1;  q = q1;  e = g_e1;  li = 0; }
    else if (b < 160) { c = b - 80;  w = w2d + c * 9;   n = 9;   wn = g_wn2d + c * 9;  p = p2d; q = q2d; e = g_e2d; li = 1; }
    else if (b < 200) { c = b - 160; w = w2p + c * 80;  n = 80;  wn = 0;               p = p2p; q = q2p; e = g_e2p; li = 2; }
    else              { c = b - 200; w = w3  + c * 360; n = 360; wn = g_wn3 + c * 360; p = p3;  q = q3;  e = g_e3;  li = 3; }
    float qt = __fdiv_rn(q[0], 100.0f);
    float qv = __fmul_rn(qt, qt);
    float s = 0.f;
    for (int i = t; i < n; i += 32) {
        float v = w[i];
        s = __fadd_rn(s, __fmul_rn(v, v));
    }
    #pragma unroll
    for (int o = 16; o > 0; o >>= 1)
        s = __fadd_rn(s, __shfl_down_sync(0xffffffffu, s, o));
    s = __shfl_sync(0xffffffffu, s, 0);
    float wnorm = __fadd_rn(sqrtf(__fadd_rn(s, EPS)), qv);
    for (int i = t; i < n; i += 32) {
        float v = __fdiv_rn(w[i], wnorm);
        if (li == 0) {
            ((float*)g_wn1p)[(c >> 1) * 150 + 2 * i + (c & 1)] = v;
        } else if (li == 2) {
            ((float*)g_wn2pp)[(c >> 1) * 160 + 2 * i + (c & 1)] = v;
        } else {
            wn[i] = v;
        }
    }
    if (t == 0) {
        float pe = __fdiv_rn(p[c], 10.0f);
        e[c] = __fmul_rn(pe, pe);
        if (c == 0) g_qv[li] = qv;
    }
}

// ---------------- layer1 patch norms ((ky,kx,c) order) ----------------------
__global__ void xnorm1_kernel(const float* x) {
    __shared__ float sx[3072];
    int img = blockIdx.x;
    const float* xp = x + img * 3072;
    for (int i = threadIdx.x; i < 3072; i += 256) sx[i] = xp[i];
    __syncthreads();
    float qv = g_qv[0];
    for (int pos = threadIdx.x; pos < 784; pos += 256) {
        int oy = pos / 28, ox = pos % 28;
        float ss = 0.f;
        #pragma unroll
        for (int ky = 0; ky < 5; ky++)
            #pragma unroll
            for (int kx = 0; kx < 5; kx++)
                #pragma unroll
                for (int c = 0; c < 3; c++) {
                    float v = sx[c * 1024 + (oy + ky) * 32 + ox + kx];
                    ss = __fadd_rn(ss, __fmul_rn(v, v));
                }
        g_xn1[img * 784 + pos] = __fadd_rn(sqrtf(__fadd_rn(ss, EPS)), qv);
    }
}

// ---------------- layer1: conv 5x5 + pool + g, channel-pair FFMA2 -----------
// block covers 8 out-channels (4 pairs); ct in {0,1} handles 2 pairs each.
__global__ void __launch_bounds__(196, 3) conv1_kernel(const float* x) {
    __shared__ float sx[3072];
    __shared__ ull   sw2[300];      // 4 channel-pairs x 75
    __shared__ float sxn[784];
    __shared__ float se[8];
    int img = blockIdx.x;
    int cb = blockIdx.y * 8;
    int tid = threadIdx.x;
    const float* xp = x + img * 3072;
    const ull* wsrc = g_wn1p + (cb >> 1) * 75;
    for (int i = tid; i < 3072; i += 196) sx[i] = xp[i];
    if (tid < 150) { sw2[tid] = wsrc[tid]; sw2[tid + 150] = wsrc[tid + 150]; }
    for (int i = tid; i < 784; i += 196) sxn[i] = g_xn1[img * 784 + i];
    if (tid < 8) se[tid] = g_e1[cb + tid];
    __syncthreads();

    int ct = tid / 98, pp = tid % 98;
    int py = pp / 7;          // pooled row 0..13
    int pq = pp % 7;          // pooled col pair 0..6
    int cx0 = 4 * pq;

    ull acc2[2][8];
    #pragma unroll
    for (int a = 0; a < 2; a++)
        #pragma unroll
        for (int j = 0; j < 8; j++) acc2[a][j] = 0ull;

    #pragma unroll 1
    for (int c = 0; c < 3; c++) {
        float xw[6][8];
        #pragma unroll
        for (int i = 0; i < 6; i++)
            #pragma unroll
            for (int j = 0; j < 8; j++)
                xw[i][j] = sx[c * 1024 + (2 * py + i) * 32 + cx0 + j];
        #pragma unroll
        for (int ky = 0; ky < 5; ky++)
            #pragma unroll
            for (int kx = 0; kx < 5; kx++) {
                ull xp2[8];
                #pragma unroll
                for (int r = 0; r < 2; r++)
                    #pragma unroll
                    for (int cl = 0; cl < 4; cl++) {
                        float v = xw[ky + r][kx + cl];
                        xp2[r * 4 + cl] = pack2(v, v);
                    }
                int widx = c * 25 + ky * 5 + kx;
                #pragma unroll
                for (int t2 = 0; t2 < 2; t2++) {
                    ull w2 = sw2[(ct * 2 + t2) * 75 + widx];
                    #pragma unroll
                    for (int j = 0; j < 8; j++)
                        acc2[t2][j] = ffma2(w2, xp2[j], acc2[t2][j]);
                }
            }
    }

    float xnv[8];
    #pragma unroll
    for (int r = 0; r < 2; r++)
        #pragma unroll
        for (int cl = 0; cl < 4; cl++)
            xnv[r * 4 + cl] = sxn[(2 * py + r) * 28 + cx0 + cl];

    #pragma unroll
    for (int t2 = 0; t2 < 2; t2++) {
        float ya[8], yb[8];
        #pragma unroll
        for (int j = 0; j < 8; j++) unpack2(acc2[t2][j], ya[j], yb[j]);
        #pragma unroll
        for (int j = 0; j < 8; j++) {
            ya[j] = __fdiv_rn(ya[j], xnv[j]);
            yb[j] = __fdiv_rn(yb[j], xnv[j]);
        }
        int co = cb + ct * 4 + 2 * t2;
        float e0 = se[ct * 4 + 2 * t2];
        float e1 = se[ct * 4 + 2 * t2 + 1];
        int o0 = ((img * 80 + co) * 14 + py) * 14 + 2 * pq;
        int o1 = o0 + 196;
        g_buf1[o0]     = scs_g(maxabs4(ya[0], ya[1], ya[4], ya[5]), e0);
        g_buf1[o0 + 1] = scs_g(maxabs4(ya[2], ya[3], ya[6], ya[7]), e0);
        g_buf1[o1]     = scs_g(maxabs4(yb[0], yb[1], yb[4], yb[5]), e1);
        g_buf1[o1 + 1] = scs_g(maxabs4(yb[2], yb[3], yb[6], yb[7]), e1);
    }
}

// ---------------- layer2 merged: depthwise + pointwise + pool + g -----------
__global__ void __launch_bounds__(384, 3) k2_kernel() {
    extern __shared__ char smc[];
    float* s_t2d = (float*)smc;                       // 11520 f = 46080 B
    ull*   s_w2  = (ull*)(smc + 46080);               // 1600 ull = 12800 B
    float* s_xn  = (float*)(smc + 46080 + 12800);     // 144 f
    float* s_e2p = s_xn + 144;                        // 40 f
    int img = blockIdx.x, tid = threadIdx.x;

    for (int i = tid; i < 1600; i += 384) s_w2[i] = g_wn2pp[i];
    if (tid < 40) s_e2p[tid] = g_e2p[tid];
    float qv2d = g_qv[1], qv2p = g_qv[2];

    // phase A: depthwise 3x3 + g -> smem; half-row tiles (chains unchanged)
    for (int tile = tid; tile < 1920; tile += 384) {
        int ch = tile / 24, rest = tile % 24;
        int oy = rest / 2, half = rest % 2;
        int ox0 = half * 6;
        const float* wp = g_wn2d + ch * 9;
        float wreg[9];
        #pragma unroll
        for (int k = 0; k < 9; k++) wreg[k] = wp[k];
        float e = g_e2d[ch];
        const float* xr = g_buf1 + (img * 80 + ch) * 196 + oy * 14 + ox0;
        float rw[3][8];
        #pragma unroll
        for (int rr = 0; rr < 3; rr++)
            #pragma unroll
            for (int j = 0; j < 8; j++) rw[rr][j] = __ldg(&xr[rr * 14 + j]);
        float* op = s_t2d + ch * 144 + oy * 12 + ox0;
        #pragma unroll
        for (int ox = 0; ox < 6; ox++) {
            float num = 0.f, ss = 0.f;
            #pragma unroll
            for (int ky = 0; ky < 3; ky++)
                #pragma unroll
                for (int kx = 0; kx < 3; kx++) {
                    float v = rw[ky][ox + kx];
                    num = fmaf(wreg[ky * 3 + kx], v, num);
                    ss  = __fadd_rn(ss, __fmul_rn(v, v));
                }
            float y = __fdiv_rn(num, __fadd_rn(sqrtf(__fadd_rn(ss, EPS)), qv2d));
            op[ox] = scs_g(y, e);
        }
    }
    __syncthreads();

    // phase B1: per-pixel channel-norm denominators (k-sequential)
    for (int pix = tid; pix < 144; pix += 384) {
        float ss = 0.f;
        for (int k = 0; k < 80; k++) {
            float v = s_t2d[k * 144 + pix];
            ss = __fadd_rn(ss, __fmul_rn(v, v));
        }
        s_xn[pix] = __fadd_rn(sqrtf(__fadd_rn(ss, EPS)), qv2p);
    }
    __syncthreads();

    // phase B2: pointwise, channel-pair FFMA2 + pool 2x2 + g
    if (tid < 360) {
        int cg = tid / 36, quad = tid % 36;   // cg covers pairs 2cg, 2cg+1
        int qy = quad / 6, qx = quad % 6;
        int p00 = (2 * qy) * 12 + 2 * qx;
        int p01 = p00 + 1, p10 = p00 + 12, p11 = p00 + 13;
        ull acc2[2][4];
        #pragma unroll
        for (int pr = 0; pr < 2; pr++)
            #pragma unroll
            for (int j = 0; j < 4; j++) acc2[pr][j] = 0ull;
        for (int k = 0; k < 80; k++) {
            float x0 = s_t2d[k * 144 + p00], x1 = s_t2d[k * 144 + p01];
            float x2 = s_t2d[k * 144 + p10], x3 = s_t2d[k * 144 + p11];
            ull xv0 = pack2(x0, x0), xv1 = pack2(x1, x1);
            ull xv2 = pack2(x2, x2), xv3 = pack2(x3, x3);
            #pragma unroll
            for (int pr = 0; pr < 2; pr++) {
                ull w2 = s_w2[(cg * 2 + pr) * 80 + k];
                acc2[pr][0] = ffma2(w2, xv0, acc2[pr][0]);
                acc2[pr][1] = ffma2(w2, xv1, acc2[pr][1]);
                acc2[pr][2] = ffma2(w2, xv2, acc2[pr][2]);
                acc2[pr][3] = ffma2(w2, xv3, acc2[pr][3]);
            }
        }
        float n0 = s_xn[p00], n1 = s_xn[p01], n2 = s_xn[p10], n3 = s_xn[p11];
        #pragma unroll
        for (int pr = 0; pr < 2; pr++) {
            float a0, b0, a1, b1, a2, b2, a3, b3;
            unpack2(acc2[pr][0], a0, b0);
            unpack2(acc2[pr][1], a1, b1);
            unpack2(acc2[pr][2], a2, b2);
            unpack2(acc2[pr][3], a3, b3);
            float va = maxabs4(__fdiv_rn(a0, n0), __fdiv_rn(a1, n1),
                               __fdiv_rn(a2, n2), __fdiv_rn(a3, n3));
            float vb = maxabs4(__fdiv_rn(b0, n0), __fdiv_rn(b1, n1),
                               __fdiv_rn(b2, n2), __fdiv_rn(b3, n3));
            int co0 = cg * 4 + 2 * pr;
            int co1 = co0 + 1;
            g_buf2[((img * 40 + co0) * 6 + qy) * 6 + qx] = scs_g(va, s_e2p[co0]);
            g_buf2[((img * 40 + co1) * 6 + qy) * 6 + qx] = scs_g(vb, s_e2p[co1]);
        }
    }
}

// ---------------- layer3: conv 3x3 (FFMA2) + pool 4x4 + g + FC --------------
__global__ void __launch_bounds__(160) layer3_kernel(const float* wo, const float* bo, float* out) {
    extern __shared__ float sm[];
    float* s_in   = sm;              // 1440
    float* s_w3   = sm + 1440;       // 14400
    float* s_wo   = s_w3 + 14400;    // 400
    float* s_e3   = s_wo + 400;      // 40
    float* s_xn   = s_e3 + 40;       // 16
    float* s_qmax = s_xn + 16;       // 160
    float* s_qmin = s_qmax + 160;    // 160
    float* s_vec  = s_qmin + 160;    // 40
    float* s_bo   = s_vec + 40;      // 16
    int img = blockIdx.x, tid = threadIdx.x;

    const float4* src = (const float4*)(g_buf2 + img * 1440);
    for (int i = tid; i < 360; i += 160) ((float4*)s_in)[i] = src[i];
    for (int i = tid; i < 3600; i += 160) ((float4*)s_w3)[i] = ((const float4*)g_wn3)[i];
    for (int i = tid; i < 400; i += 160) s_wo[i] = wo[i];
    if (tid < 40) s_e3[tid] = g_e3[tid];
    if (tid < 10) s_bo[tid] = bo[tid];
    __syncthreads();
    float qv3 = g_qv[3];

    if (tid < 16) {
        int oy = tid / 4, ox = tid % 4;
        float ss = 0.f;
        #pragma unroll
        for (int ky = 0; ky < 3; ky++)
            #pragma unroll
            for (int kx = 0; kx < 3; kx++)
                for (int c = 0; c < 40; c++) {
                    float v = s_in[c * 36 + (oy + ky) * 6 + ox + kx];
                    ss = __fadd_rn(ss, __fmul_rn(v, v));
                }
        s_xn[tid] = __fadd_rn(sqrtf(__fadd_rn(ss, EPS)), qv3);
    }
    __syncthreads();

    {   // conv with FFMA2 position pairs (halves keep their exact chains)
        int co = tid >> 2, quad = tid & 3;
        int qy = quad >> 1, qx = quad & 1;
        ull accA = 0ull, accB = 0ull;   // (pos0,pos1), (pos2,pos3)
        #pragma unroll
        for (int ky = 0; ky < 3; ky++)
            #pragma unroll
            for (int kx = 0; kx < 3; kx++)
                for (int c = 0; c < 40; c++) {
                    float w = s_w3[(co * 40 + c) * 9 + ky * 3 + kx];
                    ull w2 = pack2(w, w);
                    const float* ip = &s_in[c * 36];
                    float v0 = ip[(2 * qy + ky) * 6 + 2 * qx + kx];
                    float v1 = ip[(2 * qy + ky) * 6 + 2 * qx + 1 + kx];
                    float v2 = ip[(2 * qy + 1 + ky) * 6 + 2 * qx + kx];
                    float v3 = ip[(2 * qy + 1 + ky) * 6 + 2 * qx + 1 + kx];
                    accA = ffma2(w2, pack2(v0, v1), accA);
                    accB = ffma2(w2, pack2(v2, v3), accB);
                }
        float a0, a1, a2, a3;
        unpack2(accA, a0, a1);
        unpack2(accB, a2, a3);
        float y0 = __fdiv_rn(a0, s_xn[(2 * qy) * 4 + 2 * qx]);
        float y1 = __fdiv_rn(a1, s_xn[(2 * qy) * 4 + 2 * qx + 1]);
        float y2 = __fdiv_rn(a2, s_xn[(2 * qy + 1) * 4 + 2 * qx]);
        float y3 = __fdiv_rn(a3, s_xn[(2 * qy + 1) * 4 + 2 * qx + 1]);
        s_qmax[tid] = fmaxf(fmaxf(y0, y1), fmaxf(y2, y3));
        s_qmin[tid] = fminf(fminf(y0, y1), fminf(y2, y3));
    }
    __syncthreads();
    if (tid < 40) {
        float pmx = fmaxf(fmaxf(s_qmax[tid * 4], s_qmax[tid * 4 + 1]),
                          fmaxf(s_qmax[tid * 4 + 2], s_qmax[tid * 4 + 3]));
        float pmn = fminf(fminf(s_qmin[tid * 4], s_qmin[tid * 4 + 1]),
                          fminf(s_qmin[tid * 4 + 2], s_qmin[tid * 4 + 3]));
        float v = (pmx >= -pmn) ? pmx : pmn;
        s_vec[tid] = scs_g(v, s_e3[tid]);
    }
    __syncthreads();
    if (tid < 10) {
        float s = 0.f;
        #pragma unroll 1
        for (int c = 0; c < 40; c++) s = fmaf(s_vec[c], s_wo[tid * 40 + c], s);
        out[img * 10 + tid] = __fadd_rn(s, s_bo[tid]);
    }
}

// ---------------- launch ------------------------------------------------------
extern "C" void kernel_launch(void* const* d_in, const int* in_sizes, int n_in,
                              void* d_out, int out_size) {
    const float* x   = (const float*)d_in[0];
    const float* w1  = (const float*)d_in[1];
    const float* p1  = (const float*)d_in[2];
    const float* q1  = (const float*)d_in[3];
    const float* w2d = (const float*)d_in[4];
    const float* p2d = (const float*)d_in[5];
    const float* q2d = (const float*)d_in[6];
    const float* w2p = (const float*)d_in[7];
    const float* p2p = (const float*)d_in[8];
    const float* q2p = (const float*)d_in[9];
    const float* w3  = (const float*)d_in[10];
    const float* p3  = (const float*)d_in[11];
    const float* q3  = (const float*)d_in[12];
    const float* wo  = (const float*)d_in[13];
    const float* bo  = (const float*)d_in[14];
    float* out = (float*)d_out;

    int N = in_sizes[0] / 3072;

    static const size_t SM2 = 46080 + 12800 + 144 * 4 + 40 * 4 + 64;
    static const size_t SM3 = (1440 + 14400 + 400 + 40 + 16 + 160 + 160 + 40 + 16) * sizeof(float);
    cudaFuncSetAttribute(k2_kernel, cudaFuncAttributeMaxDynamicSharedMemorySize, (int)SM2);
    cudaFuncSetAttribute(layer3_kernel, cudaFuncAttributeMaxDynamicSharedMemorySize, (int)SM3);

    prep_kernel<<<240, 32>>>(w1, p1, q1, w2d, p2d, q2d, w2p, p2p, q2p, w3, p3, q3);
    xnorm1_kernel<<<N, 256>>>(x);
    conv1_kernel<<<dim3(N, 10), 196>>>(x);
    k2_kernel<<<N, 384, SM2>>>();
    layer3_kernel<<<N, 160, SM3>>>(wo, bo, out);
}